// round 1
// baseline (speedup 1.0000x reference)
#include <cuda_runtime.h>
#include <cuda_bf16.h>

#define TPB 256

__global__ void zero_out_kernel(float* out, int n) {
    int i = blockIdx.x * blockDim.x + threadIdx.x;
    if (i < n) out[i] = 0.0f;
}

__device__ __forceinline__ float3 load_pos(const float* __restrict__ pos, int base, int a) {
    const float* p = pos + (size_t)(base + a) * 3;
    return make_float3(__ldg(p), __ldg(p + 1), __ldg(p + 2));
}

__device__ __forceinline__ float block_reduce(float v) {
    __shared__ float sh[TPB / 32];
    #pragma unroll
    for (int o = 16; o; o >>= 1) v += __shfl_down_sync(0xffffffffu, v, o);
    int w = threadIdx.x >> 5, l = threadIdx.x & 31;
    if (l == 0) sh[w] = v;
    __syncthreads();
    if (w == 0) {
        v = (l < TPB / 32) ? sh[l] : 0.0f;
        #pragma unroll
        for (int o = 16; o; o >>= 1) v += __shfl_down_sync(0xffffffffu, v, o);
    }
    return v;
}

__global__ void bond_kernel(const float* __restrict__ pos,
                            const int* __restrict__ idcs,
                            const int* __restrict__ type,
                            const float* __restrict__ equ,
                            const float* __restrict__ kk,
                            int n, int n_atoms, float* __restrict__ out) {
    int i = blockIdx.x * blockDim.x + threadIdx.x;
    int b = blockIdx.y;
    int base = b * n_atoms;
    float e = 0.0f;
    if (i < n) {
        int a0 = __ldg(&idcs[2 * i]);
        int a1 = __ldg(&idcs[2 * i + 1]);
        float3 p0 = load_pos(pos, base, a0);
        float3 p1 = load_pos(pos, base, a1);
        float dx = p0.x - p1.x, dy = p0.y - p1.y, dz = p0.z - p1.z;
        float d = sqrtf(fmaf(dx, dx, fmaf(dy, dy, dz * dz)));
        int t = __ldg(&type[i]);
        float dd = d - __ldg(&equ[t]);
        e = __ldg(&kk[t]) * dd * dd;
    }
    float s = block_reduce(e);
    if (threadIdx.x == 0) atomicAdd(&out[b], s);
}

__global__ void angle_kernel(const float* __restrict__ pos,
                             const int* __restrict__ idcs,
                             const int* __restrict__ type,
                             const float* __restrict__ equ,
                             const float* __restrict__ kk,
                             int n, int n_atoms, float* __restrict__ out) {
    int i = blockIdx.x * blockDim.x + threadIdx.x;
    int b = blockIdx.y;
    int base = b * n_atoms;
    float e = 0.0f;
    if (i < n) {
        int a0 = __ldg(&idcs[3 * i]);
        int a1 = __ldg(&idcs[3 * i + 1]);
        int a2 = __ldg(&idcs[3 * i + 2]);
        float3 p0 = load_pos(pos, base, a0);
        float3 p1 = load_pos(pos, base, a1);
        float3 p2 = load_pos(pos, base, a2);
        float v1x = p0.x - p1.x, v1y = p0.y - p1.y, v1z = p0.z - p1.z;
        float v2x = p2.x - p1.x, v2y = p2.y - p1.y, v2z = p2.z - p1.z;
        float n1 = fmaf(v1x, v1x, fmaf(v1y, v1y, v1z * v1z));
        float n2 = fmaf(v2x, v2x, fmaf(v2y, v2y, v2z * v2z));
        float dot = fmaf(v1x, v2x, fmaf(v1y, v2y, v1z * v2z));
        float c = dot * rsqrtf(n1) * rsqrtf(n2);
        c = fminf(1.0f, fmaxf(-1.0f, c));
        float theta = acosf(c);
        int t = __ldg(&type[i]);
        float dd = theta - __ldg(&equ[t]);
        e = __ldg(&kk[t]) * dd * dd;
    }
    float s = block_reduce(e);
    if (threadIdx.x == 0) atomicAdd(&out[b], s);
}

__device__ __forceinline__ float dihedral(const float* __restrict__ pos, int base,
                                          int a0, int a1, int a2, int a3) {
    float3 p0 = load_pos(pos, base, a0);
    float3 p1 = load_pos(pos, base, a1);
    float3 p2 = load_pos(pos, base, a2);
    float3 p3 = load_pos(pos, base, a3);
    // b0 = p0 - p1 ; b1 = normalize(p2 - p1) ; b2 = p3 - p2
    float b0x = p0.x - p1.x, b0y = p0.y - p1.y, b0z = p0.z - p1.z;
    float b1x = p2.x - p1.x, b1y = p2.y - p1.y, b1z = p2.z - p1.z;
    float b2x = p3.x - p2.x, b2y = p3.y - p2.y, b2z = p3.z - p2.z;
    float inv = rsqrtf(fmaf(b1x, b1x, fmaf(b1y, b1y, b1z * b1z)));
    b1x *= inv; b1y *= inv; b1z *= inv;
    float d0 = fmaf(b0x, b1x, fmaf(b0y, b1y, b0z * b1z));
    float d2 = fmaf(b2x, b1x, fmaf(b2y, b1y, b2z * b1z));
    float vx = b0x - d0 * b1x, vy = b0y - d0 * b1y, vz = b0z - d0 * b1z;
    float wx = b2x - d2 * b1x, wy = b2y - d2 * b1y, wz = b2z - d2 * b1z;
    float x = fmaf(vx, wx, fmaf(vy, wy, vz * wz));
    // cross(b1, v)
    float cx = b1y * vz - b1z * vy;
    float cy = b1z * vx - b1x * vz;
    float cz = b1x * vy - b1y * vx;
    float y = fmaf(cx, wx, fmaf(cy, wy, cz * wz));
    return atan2f(y, x);
}

__global__ void improper_kernel(const float* __restrict__ pos,
                                const int* __restrict__ idcs,
                                const int* __restrict__ type,
                                const float* __restrict__ equ,
                                const float* __restrict__ kk,
                                int n, int n_atoms, float* __restrict__ out) {
    int i = blockIdx.x * blockDim.x + threadIdx.x;
    int b = blockIdx.y;
    int base = b * n_atoms;
    float e = 0.0f;
    if (i < n) {
        int4 a = __ldg((const int4*)idcs + i);
        float phi = dihedral(pos, base, a.x, a.y, a.z, a.w);
        int t = __ldg(&type[i]);
        float dd = phi - __ldg(&equ[t]);
        e = __ldg(&kk[t]) * dd * dd;
    }
    float s = block_reduce(e);
    if (threadIdx.x == 0) atomicAdd(&out[b], s);
}

__global__ void proper_kernel(const float* __restrict__ pos,
                              const int* __restrict__ idcs,
                              const float* __restrict__ phase,
                              const float* __restrict__ cst,
                              const float* __restrict__ mul,
                              int n, int n_atoms, float* __restrict__ out) {
    int i = blockIdx.x * blockDim.x + threadIdx.x;
    int b = blockIdx.y;
    int base = b * n_atoms;
    float e = 0.0f;
    if (i < n) {
        int4 a = __ldg((const int4*)idcs + i);
        float phi = dihedral(pos, base, a.x, a.y, a.z, a.w);
        float arg = fmaf(__ldg(&mul[i]), phi, -__ldg(&phase[i]));
        e = __ldg(&cst[i]) * (1.0f + cosf(arg));
    }
    float s = block_reduce(e);
    if (threadIdx.x == 0) atomicAdd(&out[b], s);
}

extern "C" void kernel_launch(void* const* d_in, const int* in_sizes, int n_in,
                              void* d_out, int out_size) {
    const float* pos            = (const float*)d_in[0];
    const int*   bond_idcs      = (const int*)d_in[1];
    const int*   bond_type      = (const int*)d_in[2];
    const float* equ_bond       = (const float*)d_in[3];
    const float* k_bond         = (const float*)d_in[4];
    const int*   angle_idcs     = (const int*)d_in[5];
    const int*   angle_type     = (const int*)d_in[6];
    const float* equ_angle      = (const float*)d_in[7];
    const float* k_angle        = (const float*)d_in[8];
    const int*   improper_idcs  = (const int*)d_in[9];
    const int*   improper_type  = (const int*)d_in[10];
    const float* equ_improper   = (const float*)d_in[11];
    const float* k_improper     = (const float*)d_in[12];
    const int*   proper_idcs    = (const int*)d_in[13];
    const float* proper_phase   = (const float*)d_in[14];
    const float* proper_const   = (const float*)d_in[15];
    const float* proper_mul     = (const float*)d_in[16];
    float* out = (float*)d_out;

    int B       = out_size;                 // 64
    int n_bond  = in_sizes[2];
    int n_angle = in_sizes[6];
    int n_improper = in_sizes[10];
    int n_proper   = in_sizes[14];
    int n_atoms = in_sizes[0] / (3 * B);

    zero_out_kernel<<<1, 64>>>(out, B);

    dim3 gb((n_bond + TPB - 1) / TPB, B);
    bond_kernel<<<gb, TPB>>>(pos, bond_idcs, bond_type, equ_bond, k_bond,
                             n_bond, n_atoms, out);

    dim3 ga((n_angle + TPB - 1) / TPB, B);
    angle_kernel<<<ga, TPB>>>(pos, angle_idcs, angle_type, equ_angle, k_angle,
                              n_angle, n_atoms, out);

    dim3 gi((n_improper + TPB - 1) / TPB, B);
    improper_kernel<<<gi, TPB>>>(pos, improper_idcs, improper_type, equ_improper,
                                 k_improper, n_improper, n_atoms, out);

    dim3 gp((n_proper + TPB - 1) / TPB, B);
    proper_kernel<<<gp, TPB>>>(pos, proper_idcs, proper_phase, proper_const,
                               proper_mul, n_proper, n_atoms, out);
}